// round 6
// baseline (speedup 1.0000x reference)
#include <cuda_runtime.h>
#include <cstdint>

#define NUM_CLASSES 7
#define NTHREADS 256
#define ROWS_TILE 1024            // rows per block tile
#define L4_TILE  (ROWS_TILE * 7 / 4)   // 1792 float4 of logits
#define R4_TILE  (ROWS_TILE * 3 / 4)   // 768  int4 of repr
#define B4_TILE  (ROWS_TILE / 4)       // 256  int4 of labels
#define NBLOCKS  740              // 148 SMs * 5

__device__ double g_sum = 0.0;
__device__ unsigned int g_done_count = 0;

__global__ __launch_bounds__(NTHREADS)
void hinge_tiled_kernel(const float4* __restrict__ logit4,
                        const int4* __restrict__ label4,
                        const int4* __restrict__ repr4,
                        const float* __restrict__ logit_s,
                        const int* __restrict__ label_s,
                        const int* __restrict__ repr_s,
                        int ntiles, int Bmain, int B,
                        float* __restrict__ out)
{
    __shared__ float4 slog[L4_TILE];   // 28672 B
    __shared__ int4   srep[R4_TILE];   // 12288 B
    __shared__ int4   slab[B4_TILE];   //  4096 B

    const int t = threadIdx.x;
    float acc = 0.0f;

    const int total_l4 = (Bmain / 4) * 7;
    const int total_r4 = (Bmain / 4) * 3;
    const int total_b4 = Bmain / 4;

    for (int tile = blockIdx.x; tile < ntiles; tile += gridDim.x) {
        const int base_row = tile * ROWS_TILE;
        const bool full = (base_row + ROWS_TILE) <= Bmain;

        // ---- coalesced staged load: every LDG.128 covers 4 consecutive lines ----
        if (full) {
            const int bl = tile * L4_TILE;
            #pragma unroll
            for (int k = 0; k < 7; k++)
                slog[t + k * NTHREADS] = __ldcs(logit4 + bl + t + k * NTHREADS);
            const int br = tile * R4_TILE;
            #pragma unroll
            for (int k = 0; k < 3; k++)
                srep[t + k * NTHREADS] = __ldcs(repr4 + br + t + k * NTHREADS);
            slab[t] = __ldcs(label4 + tile * B4_TILE + t);
        } else {
            const int bl = tile * L4_TILE;
            #pragma unroll
            for (int k = 0; k < 7; k++) {
                int idx = bl + t + k * NTHREADS;
                if (idx < total_l4) slog[t + k * NTHREADS] = __ldcs(logit4 + idx);
            }
            const int br = tile * R4_TILE;
            #pragma unroll
            for (int k = 0; k < 3; k++) {
                int idx = br + t + k * NTHREADS;
                if (idx < total_r4) srep[t + k * NTHREADS] = __ldcs(repr4 + idx);
            }
            int idx = tile * B4_TILE + t;
            if (idx < total_b4) slab[t] = __ldcs(label4 + idx);
        }
        __syncthreads();

        // ---- compute: thread t owns rows [4t, 4t+4) of the tile ----
        // LDS.128 strides 112B/48B/16B are all odd multiples of 16B -> conflict-free.
        const int row0 = base_row + t * 4;
        if (full || (row0 + 4) <= Bmain) {
            float4 L[7];
            #pragma unroll
            for (int k = 0; k < 7; k++) L[k] = slog[t * 7 + k];
            const float* lf = reinterpret_cast<const float*>(L);

            int4 r[3];
            #pragma unroll
            for (int k = 0; k < 3; k++) r[k] = srep[t * 3 + k];
            const int* rv = reinterpret_cast<const int*>(r);

            int4 lab = slab[t];
            const int* lb = reinterpret_cast<const int*>(&lab);

            #pragma unroll
            for (int row = 0; row < 4; row++) {
                unsigned mask = (1u << rv[row * 3 + 0])
                              | (1u << rv[row * 3 + 1])
                              | (1u << rv[row * 3 + 2]);
                float tg = (lb[row] == 1) ? 1.0f : 0.0f;
                #pragma unroll
                for (int j = 0; j < NUM_CLASSES; j++) {
                    float d = lf[row * NUM_CLASSES + j] - tg;
                    acc += ((mask >> j) & 1u) ? fabsf(d) : fmaxf(d, 0.0f);
                }
            }
        } else if (row0 < Bmain) {
            // partial group inside last tile (Bmain % 4 == 0, so whole rows only)
            const float* lfs = reinterpret_cast<const float*>(slog);
            const int* rvs = reinterpret_cast<const int*>(srep);
            const int* lbs = reinterpret_cast<const int*>(slab);
            for (int row = 0; row < 4 && (row0 + row) < Bmain; row++) {
                int lr = t * 4 + row;
                unsigned mask = (1u << rvs[lr * 3 + 0])
                              | (1u << rvs[lr * 3 + 1])
                              | (1u << rvs[lr * 3 + 2]);
                float tg = (lbs[lr] == 1) ? 1.0f : 0.0f;
                for (int j = 0; j < NUM_CLASSES; j++) {
                    float d = lfs[lr * NUM_CLASSES + j] - tg;
                    acc += ((mask >> j) & 1u) ? fabsf(d) : fmaxf(d, 0.0f);
                }
            }
        }
        __syncthreads();   // protect SMEM before next tile's loads
    }

    // scalar remainder rows (B % 4 != 0), direct from gmem
    if (blockIdx.x == 0 && t == 0) {
        for (int row = Bmain; row < B; row++) {
            unsigned mask = (1u << repr_s[(size_t)row * 3 + 0])
                          | (1u << repr_s[(size_t)row * 3 + 1])
                          | (1u << repr_s[(size_t)row * 3 + 2]);
            float tg = (label_s[row] == 1) ? 1.0f : 0.0f;
            for (int j = 0; j < NUM_CLASSES; j++) {
                float d = logit_s[(size_t)row * NUM_CLASSES + j] - tg;
                acc += ((mask >> j) & 1u) ? fabsf(d) : fmaxf(d, 0.0f);
            }
        }
    }

    // intra-block reduce
    #pragma unroll
    for (int o = 16; o > 0; o >>= 1)
        acc += __shfl_down_sync(0xffffffffu, acc, o);

    __shared__ float s[NTHREADS / 32];
    if ((t & 31) == 0) s[t >> 5] = acc;
    __syncthreads();

    // tiny epilogue: one f64 atomic per block + last-block scalar writeout
    if (t == 0) {
        float v = 0.0f;
        #pragma unroll
        for (int w = 0; w < NTHREADS / 32; w++) v += s[w];

        atomicAdd(&g_sum, (double)v);
        __threadfence();
        unsigned int prev = atomicAdd(&g_done_count, 1u);
        if (prev == (unsigned)gridDim.x - 1u) {
            double total = atomicAdd(&g_sum, 0.0);
            *out = (float)total;
            g_sum = 0.0;
            g_done_count = 0u;
        }
    }
}

extern "C" void kernel_launch(void* const* d_in, const int* in_sizes, int n_in,
                              void* d_out, int out_size)
{
    // logit is [B,7] fp32 at d_in[0] (largest input, 7-multiple element count).
    const float* logit = (const float*)d_in[0];
    const int B = in_sizes[0] / NUM_CLASSES;

    // Disambiguate label ([B] int32) vs repr_num ([B,3] int32) by element count.
    const int* label;
    const int* repr;
    if (in_sizes[1] == B) {
        label = (const int*)d_in[1];
        repr  = (const int*)d_in[2];
    } else {
        label = (const int*)d_in[2];
        repr  = (const int*)d_in[1];
    }

    const int Bmain = (B / 4) * 4;
    const int ntiles = (Bmain + ROWS_TILE - 1) / ROWS_TILE;

    hinge_tiled_kernel<<<NBLOCKS, NTHREADS>>>(
        (const float4*)logit, (const int4*)label, (const int4*)repr,
        logit, label, repr, ntiles, Bmain, B, (float*)d_out);
}

// round 7
// speedup vs baseline: 1.1858x; 1.1858x over previous
#include <cuda_runtime.h>
#include <cstdint>

#define NUM_CLASSES 7
#define NTHREADS 256
#define ROWS_TILE 512                 // rows per tile (multiple of 4)
#define LOG_BYTES (ROWS_TILE * 28)    // 14336
#define REP_BYTES (ROWS_TILE * 12)    //  6144
#define LAB_BYTES (ROWS_TILE * 4)     //  2048
#define BUF_BYTES (LOG_BYTES + REP_BYTES + LAB_BYTES)  // 22528
#define NBLOCKS 592                   // 148 SMs * 4 resident

__device__ double g_sum = 0.0;
__device__ unsigned int g_done_count = 0;

__device__ __forceinline__ uint32_t smem_u32(const void* p) {
    uint32_t a;
    asm("{ .reg .u64 t; cvta.to.shared.u64 t, %1; cvt.u32.u64 %0, t; }"
        : "=r"(a) : "l"(p));
    return a;
}

__device__ __forceinline__ void mbar_init(uint32_t mbar, uint32_t count) {
    asm volatile("mbarrier.init.shared.b64 [%0], %1;" :: "r"(mbar), "r"(count) : "memory");
}
__device__ __forceinline__ void mbar_expect_tx(uint32_t mbar, uint32_t bytes) {
    asm volatile("mbarrier.arrive.expect_tx.shared.b64 _, [%0], %1;"
                 :: "r"(mbar), "r"(bytes) : "memory");
}
__device__ __forceinline__ void bulk_g2s(uint32_t sdst, const void* gsrc,
                                         uint32_t bytes, uint32_t mbar) {
    asm volatile("cp.async.bulk.shared::cta.global.mbarrier::complete_tx::bytes "
                 "[%0], [%1], %2, [%3];"
                 :: "r"(sdst), "l"(gsrc), "r"(bytes), "r"(mbar) : "memory");
}
__device__ __forceinline__ void mbar_wait(uint32_t mbar, uint32_t parity) {
    asm volatile(
        "{\n\t"
        ".reg .pred P;\n\t"
        "W%=:\n\t"
        "mbarrier.try_wait.parity.acquire.cta.shared::cta.b64 P, [%0], %1, 0x989680;\n\t"
        "@P bra D%=;\n\t"
        "bra W%=;\n\t"
        "D%=:\n\t"
        "}" :: "r"(mbar), "r"(parity) : "memory");
}

__global__ __launch_bounds__(NTHREADS)
void hinge_bulk_kernel(const char* __restrict__ logit_g,
                       const char* __restrict__ label_g,
                       const char* __restrict__ repr_g,
                       const float* __restrict__ logit_s,
                       const int* __restrict__ label_s,
                       const int* __restrict__ repr_s,
                       int ntiles, int Bmain, int B,
                       float* __restrict__ out)
{
    __shared__ char sbuf[2 * BUF_BYTES];           // 45056 B, 16B-aligned regions
    __shared__ __align__(8) unsigned long long smbar[2];

    const int t = threadIdx.x;
    const uint32_t mb0 = smem_u32(&smbar[0]);
    const uint32_t mb1 = smem_u32(&smbar[1]);

    if (t == 0) { mbar_init(mb0, 1); mbar_init(mb1, 1); }
    __syncthreads();

    float acc = 0.0f;
    int ph[2] = {0, 0};

    // issue a tile's 3 bulk copies into buffer b
    auto issue = [&](int b, int tile) {
        const int base_row = tile * ROWS_TILE;
        const int rows = min(ROWS_TILE, Bmain - base_row);
        const uint32_t lb = (uint32_t)(rows * 28);
        const uint32_t rb = (uint32_t)(rows * 12);
        const uint32_t bb = (uint32_t)(rows * 4);
        const uint32_t mb = b ? mb1 : mb0;
        const uint32_t sb = smem_u32(sbuf) + (uint32_t)b * BUF_BYTES;
        mbar_expect_tx(mb, lb + rb + bb);
        bulk_g2s(sb,                         logit_g + (size_t)base_row * 28, lb, mb);
        bulk_g2s(sb + LOG_BYTES,             repr_g  + (size_t)base_row * 12, rb, mb);
        bulk_g2s(sb + LOG_BYTES + REP_BYTES, label_g + (size_t)base_row * 4,  bb, mb);
    };

    int tile = blockIdx.x;
    int buf = 0;
    if (tile < ntiles && t == 0) issue(0, tile);

    for (; tile < ntiles; tile += gridDim.x) {
        const int ntile = tile + gridDim.x;
        const int nbuf = buf ^ 1;
        if (ntile < ntiles && t == 0) issue(nbuf, ntile);   // prefetch next

        mbar_wait(buf ? mb1 : mb0, ph[buf]);
        ph[buf] ^= 1;

        const char* bp = sbuf + buf * BUF_BYTES;
        const int rows = min(ROWS_TILE, Bmain - tile * ROWS_TILE);

        // thread t owns local rows 2t, 2t+1 (rows is a multiple of 4)
        if (2 * t + 1 < rows) {
            // logits: 14 floats at byte offset 56*t (8B aligned) -> 7x LDS.64
            const float2* lp = reinterpret_cast<const float2*>(bp + 56 * t);
            float2 l[7];
            #pragma unroll
            for (int k = 0; k < 7; k++) l[k] = lp[k];
            const float* lf = reinterpret_cast<const float*>(l);

            // repr: 6 ints at byte offset 24*t -> 3x LDS.64
            const int2* rp = reinterpret_cast<const int2*>(bp + LOG_BYTES + 24 * t);
            int2 r[3];
            #pragma unroll
            for (int k = 0; k < 3; k++) r[k] = rp[k];
            const int* rv = reinterpret_cast<const int*>(r);

            // labels: 2 ints at byte offset 8*t -> 1x LDS.64
            int2 lab = *reinterpret_cast<const int2*>(bp + LOG_BYTES + REP_BYTES + 8 * t);
            const int* lbv = reinterpret_cast<const int*>(&lab);

            #pragma unroll
            for (int row = 0; row < 2; row++) {
                unsigned mask = (1u << rv[row * 3 + 0])
                              | (1u << rv[row * 3 + 1])
                              | (1u << rv[row * 3 + 2]);
                float tg = (lbv[row] == 1) ? 1.0f : 0.0f;
                #pragma unroll
                for (int j = 0; j < NUM_CLASSES; j++) {
                    float d = lf[row * NUM_CLASSES + j] - tg;
                    acc += ((mask >> j) & 1u) ? fabsf(d) : fmaxf(d, 0.0f);
                }
            }
        }
        __syncthreads();   // all reads of this buffer done before it is refilled
        buf = nbuf;
    }

    // remainder rows (B % 4 != 0), direct from gmem
    if (blockIdx.x == 0 && t == 0) {
        for (int row = Bmain; row < B; row++) {
            unsigned mask = (1u << repr_s[(size_t)row * 3 + 0])
                          | (1u << repr_s[(size_t)row * 3 + 1])
                          | (1u << repr_s[(size_t)row * 3 + 2]);
            float tg = (label_s[row] == 1) ? 1.0f : 0.0f;
            for (int j = 0; j < NUM_CLASSES; j++) {
                float d = logit_s[(size_t)row * NUM_CLASSES + j] - tg;
                acc += ((mask >> j) & 1u) ? fabsf(d) : fmaxf(d, 0.0f);
            }
        }
    }

    // intra-block reduce
    #pragma unroll
    for (int o = 16; o > 0; o >>= 1)
        acc += __shfl_down_sync(0xffffffffu, acc, o);

    __shared__ float sred[NTHREADS / 32];
    if ((t & 31) == 0) sred[t >> 5] = acc;
    __syncthreads();

    // tiny epilogue: one f64 atomic per block + last-block scalar writeout
    if (t == 0) {
        float v = 0.0f;
        #pragma unroll
        for (int w = 0; w < NTHREADS / 32; w++) v += sred[w];

        atomicAdd(&g_sum, (double)v);
        __threadfence();
        unsigned int prev = atomicAdd(&g_done_count, 1u);
        if (prev == (unsigned)gridDim.x - 1u) {
            double total = atomicAdd(&g_sum, 0.0);
            *out = (float)total;
            g_sum = 0.0;
            g_done_count = 0u;
        }
    }
}

extern "C" void kernel_launch(void* const* d_in, const int* in_sizes, int n_in,
                              void* d_out, int out_size)
{
    // logit is [B,7] fp32 at d_in[0] (largest input, 7-multiple element count).
    const float* logit = (const float*)d_in[0];
    const int B = in_sizes[0] / NUM_CLASSES;

    // Disambiguate label ([B] int32) vs repr_num ([B,3] int32) by element count.
    const int* label;
    const int* repr;
    if (in_sizes[1] == B) {
        label = (const int*)d_in[1];
        repr  = (const int*)d_in[2];
    } else {
        label = (const int*)d_in[2];
        repr  = (const int*)d_in[1];
    }

    const int Bmain = (B / 4) * 4;
    const int ntiles = (Bmain + ROWS_TILE - 1) / ROWS_TILE;

    hinge_bulk_kernel<<<NBLOCKS, NTHREADS>>>(
        (const char*)logit, (const char*)label, (const char*)repr,
        logit, label, repr, ntiles, Bmain, B, (float*)d_out);
}